// round 14
// baseline (speedup 1.0000x reference)
#include <cuda_runtime.h>
#include <cuda_fp16.h>
#include <math.h>
#include <stdint.h>

#define BATCH   8192
#define DIM     256
#define KRED    1024
#define NCOEF   5
#define NLAYERS 2
#define LN_EPS  1e-6f

// ---------------------------------------------------------------------------
// Scratch
// ---------------------------------------------------------------------------
__device__ float  g_p0[2 * BATCH * DIM];        // layer-0 K-split partials
__device__ float  g_p1[2 * BATCH * DIM];        // layer-1 K-split partials
__device__ __half g_Bn[NLAYERS * DIM * KRED];
__device__ float  g_bias[NLAYERS * DIM];
__device__ float  g_jc[NLAYERS * 8];

// ---------------------------------------------------------------------------
// Helpers
// ---------------------------------------------------------------------------
__device__ __forceinline__ uint32_t smem_u32(const void* p) {
    uint32_t a;
    asm("{ .reg .u64 t; cvta.to.shared.u64 t, %1; cvt.u32.u64 %0, t; }"
        : "=r"(a) : "l"(p));
    return a;
}
__device__ __forceinline__ float tanh_fast(float v) {
    float r;
    asm("tanh.approx.f32 %0, %1;" : "=f"(r) : "f"(v));
    return r;
}
__device__ __forceinline__ void mma_f16_16n8k16(float* d, const uint32_t* a,
                                                const uint32_t* b) {
    asm volatile(
        "mma.sync.aligned.m16n8k16.row.col.f32.f16.f16.f32 "
        "{%0,%1,%2,%3}, {%4,%5,%6,%7}, {%8,%9}, {%0,%1,%2,%3};"
        : "+f"(d[0]), "+f"(d[1]), "+f"(d[2]), "+f"(d[3])
        : "r"(a[0]), "r"(a[1]), "r"(a[2]), "r"(a[3]),
          "r"(b[0]), "r"(b[1]));
}
#define LDSM4(r0, r1, r2, r3, addr) \
    asm volatile("ldmatrix.sync.aligned.m8n8.x4.shared.b16 {%0,%1,%2,%3}, [%4];" \
        : "=r"(r0), "=r"(r1), "=r"(r2), "=r"(r3) : "r"(addr))
#define CP_ASYNC16(dst, src) \
    asm volatile("cp.async.ca.shared.global [%0], [%1], 16;" \
        :: "r"(dst), "l"(src))
#define CP_COMMIT()  asm volatile("cp.async.commit_group;" ::: "memory")
#define CP_WAIT1()   asm volatile("cp.async.wait_group 1;"  ::: "memory")

// ---------------------------------------------------------------------------
// build Bn[l][o][k], k = i*4 + (c-1), fp16
// ---------------------------------------------------------------------------
__global__ void build_Bn(const float* __restrict__ coefs,
                         __half* __restrict__ Bn) {
    int idx = blockIdx.x * blockDim.x + threadIdx.x;
    const int total = NLAYERS * DIM * KRED;
    if (idx >= total) return;
    int k = idx & (KRED - 1);
    int o = (idx >> 10) & (DIM - 1);
    int l = idx >> 18;
    int i = k >> 2;
    int c = (k & 3) + 1;
    Bn[idx] = __float2half_rn(
        coefs[(((size_t)(l * DIM + i)) * DIM + o) * NCOEF + c]);
}

// ---------------------------------------------------------------------------
// bias[l][o] = sum_i coefs[l][i][o][0]; Jacobi coefficient table
// ---------------------------------------------------------------------------
__global__ void __launch_bounds__(128)
build_bias(const float* __restrict__ coefs, const float* __restrict__ alphas,
           float* __restrict__ bias, float* __restrict__ jc) {
    int lo = blockIdx.x;
    int l = lo >> 8, o = lo & 255;
    float s = 0.0f;
    for (int i = threadIdx.x; i < DIM; i += 128)
        s += coefs[(((size_t)(l * DIM + i)) * DIM + o) * NCOEF];
    #pragma unroll
    for (int off = 16; off; off >>= 1) s += __shfl_xor_sync(0xFFFFFFFFu, s, off);
    __shared__ float red[4];
    if ((threadIdx.x & 31) == 0) red[threadIdx.x >> 5] = s;
    __syncthreads();
    if (threadIdx.x == 0)
        bias[lo] = red[0] + red[1] + red[2] + red[3];

    if (o == 0 && threadIdx.x == 0) {
        float a = tanhf(alphas[l]);
        jc[l * 8 + 0] = a + 1.0f;
        #pragma unroll
        for (int k = 2; k <= 4; k++) {
            float kf = (float)k;
            float t  = 2.0f * kf + 2.0f * a;
            float A  = 2.0f * kf * (kf + 2.0f * a) * (t - 2.0f);
            float B  = (t - 1.0f) * t * (t - 2.0f);
            float Cc = 2.0f * (kf + a - 1.0f) * (kf + a - 1.0f) * t;
            jc[l * 8 + (k - 1)]     = B / A;
            jc[l * 8 + 3 + (k - 1)] = Cc / A;
        }
        jc[l * 8 + 7] = 0.0f;
    }
}

// ---------------------------------------------------------------------------
// combine: out = p0 + p1 (vectorized)
// ---------------------------------------------------------------------------
__global__ void __launch_bounds__(256)
combine(const float* __restrict__ p, float* __restrict__ out) {
    int idx = blockIdx.x * blockDim.x + threadIdx.x;   // float4 index
    const float4 a = ((const float4*)p)[idx];
    const float4 b = ((const float4*)(p + BATCH * DIM))[idx];
    float4 o;
    o.x = a.x + b.x; o.y = a.y + b.y; o.z = a.z + b.z; o.w = a.w + b.w;
    ((float4*)out)[idx] = o;
}

// ---------------------------------------------------------------------------
// Fused layer, split-K x2: LN + tanh + Jacobi A-gen + fp16 HMMA GEMM.
// CTA tile 64(M) x 128(N) x K/2, 256 threads, 8 warps (2m x 4n, 32x32).
// grid (128, 2, 2) = 512 CTAs. Input h = h0 (+ h1 if h1 != null).
// kz=0 adds bias. Output partial -> Cpart + kz*BATCH*DIM.
// ---------------------------------------------------------------------------
#define BK        64
#define NCH_PER   8                   // chunks per K-split half
#define ROWB      144
#define A_TILE_B  (64 * ROWB)         // 9216
#define B_TILE_B  (128 * ROWB)        // 18432
#define SM_A      1024
#define SM_B      (1024 + 2 * A_TILE_B)   // 19456
#define SMEM_FUSED_BYTES (1024 + 2 * A_TILE_B + 3 * B_TILE_B)  // 74752

__global__ void __launch_bounds__(256, 3)
fused_layer(const float* __restrict__ h0,
            const float* __restrict__ h1,
            const __half* __restrict__ Bn,
            const float* __restrict__ biasP0,
            const float* __restrict__ lnscale,
            const float* __restrict__ lnbias,
            const float* __restrict__ jc,
            float* __restrict__ Cpart) {
    extern __shared__ char sm[];
    const uint32_t sb = smem_u32(sm);
    float2* stats = (float2*)sm;      // 64 rows

    const int tid = threadIdx.x;
    const int lid = tid & 31;
    const int wid = tid >> 5;
    const int warp_m = wid & 1;
    const int warp_n = wid >> 1;
    const int qr = lid >> 2;
    const int qc = lid & 3;

    const int bm = blockIdx.x * 64;
    const int bn = blockIdx.y * 128;
    const int kz = blockIdx.z;           // 0/1 K-split half
    const int ch0 = kz * NCH_PER;        // first global chunk

    float* C = Cpart + (size_t)kz * BATCH * DIM;

    // B stage loader
    auto issueB = [&](int stage, int ch) {   // ch = local chunk
        const uint32_t st = sb + SM_B + (uint32_t)stage * B_TILE_B;
        const int chg = ch0 + ch;
        #pragma unroll
        for (int it = 0; it < 4; it++) {
            int idx = tid + it * 256;
            int row = idx >> 3, q8 = idx & 7;
            const __half* gb = Bn + (size_t)(bn + row) * KRED + chg * BK + q8 * 8;
            CP_ASYNC16(st + row * ROWB + q8 * 16, gb);
        }
        CP_COMMIT();
    };

    // h prefetch: row r0 = tid>>2, float4 col (tid&3)*4 within chunk's 16 dims
    const int i4 = tid & 3;
    const int r0 = tid >> 2;
    auto loadH = [&](int ch, float4& v) {
        const size_t off = (size_t)(bm + r0) * DIM + (ch0 + ch) * 16 + i4 * 4;
        v = *(const float4*)(h0 + off);
        if (h1) {
            float4 w = *(const float4*)(h1 + off);
            v.x += w.x; v.y += w.y; v.z += w.z; v.w += w.w;
        }
    };

    // A generation
    auto genA = [&](int ch, int abuf, float4 v) {
        float4 j0 = __ldg((const float4*)jc);
        float4 j1 = __ldg((const float4*)jc + 1);
        const int cbase = (ch0 + ch) * 16 + i4 * 4;
        float4 sc = *(const float4*)(lnscale + cbase);
        float4 bi = *(const float4*)(lnbias  + cbase);
        float2 st = stats[r0];
        float xv[4]  = {v.x, v.y, v.z, v.w};
        float scv[4] = {sc.x, sc.y, sc.z, sc.w};
        float biv[4] = {bi.x, bi.y, bi.z, bi.w};
        uint32_t oh[8];
        #pragma unroll
        for (int e = 0; e < 4; e++) {
            float x  = tanh_fast((xv[e] - st.x) * st.y * scv[e] + biv[e]);
            float P1 = j0.x * x;
            float P2 = j0.y * x * P1 - j1.x;
            float P3 = j0.z * x * P2 - j1.y * P1;
            float P4 = j0.w * x * P3 - j1.z * P2;
            __half2 h0p = __floats2half2_rn(P1, P2);
            __half2 h1p = __floats2half2_rn(P3, P4);
            oh[2 * e]     = *(uint32_t*)&h0p;
            oh[2 * e + 1] = *(uint32_t*)&h1p;
        }
        uint4* dst = (uint4*)(sm + SM_A + abuf * A_TILE_B + r0 * ROWB + i4 * 32);
        dst[0] = make_uint4(oh[0], oh[1], oh[2], oh[3]);
        dst[1] = make_uint4(oh[4], oh[5], oh[6], oh[7]);
    };

    // -------- prologue ------------------------------------------------------
    issueB(0, 0);
    issueB(1, 1);

    {   // LN stats over full DIM of (h0 [+ h1]): warp w -> rows w*8 .. w*8+7
        #pragma unroll 1
        for (int j = 0; j < 8; j++) {
            int row = wid * 8 + j;
            const float4* pa = (const float4*)(h0 + (size_t)(bm + row) * DIM) + lid * 2;
            float4 u = pa[0], v = pa[1];
            if (h1) {
                const float4* pb = (const float4*)(h1 + (size_t)(bm + row) * DIM) + lid * 2;
                float4 u2 = pb[0], v2 = pb[1];
                u.x += u2.x; u.y += u2.y; u.z += u2.z; u.w += u2.w;
                v.x += v2.x; v.y += v2.y; v.z += v2.z; v.w += v2.w;
            }
            float s  = u.x + u.y + u.z + u.w + v.x + v.y + v.z + v.w;
            float s2 = u.x*u.x + u.y*u.y + u.z*u.z + u.w*u.w
                     + v.x*v.x + v.y*v.y + v.z*v.z + v.w*v.w;
            #pragma unroll
            for (int off = 16; off; off >>= 1) {
                s  += __shfl_xor_sync(0xFFFFFFFFu, s,  off);
                s2 += __shfl_xor_sync(0xFFFFFFFFu, s2, off);
            }
            if (lid == 0) {
                float mu  = s * (1.0f / DIM);
                float var = s2 * (1.0f / DIM) - mu * mu;
                stats[row] = make_float2(mu, rsqrtf(var + LN_EPS));
            }
        }
    }
    __syncthreads();              // stats visible

    float4 hc, hn;
    loadH(0, hc);
    genA(0, 0, hc);
    loadH(1, hn);

    CP_WAIT1();                   // B(0) arrived
    __syncthreads();              // A(0) + B(0) visible

    // ldmatrix lane offsets
    const uint32_t a_loff =
        (uint32_t)((warp_m * 32 + (lid & 15)) * ROWB + ((lid >> 4) << 4));
    const uint32_t b_loff =
        (uint32_t)((warp_n * 32 + ((lid & 7) | ((lid >> 4) << 3))) * ROWB +
                   (((lid >> 3) & 1) << 4));

    float acc[2][4][4];
    #pragma unroll
    for (int mt = 0; mt < 2; mt++)
        #pragma unroll
        for (int nt = 0; nt < 4; nt++)
            #pragma unroll
            for (int j = 0; j < 4; j++) acc[mt][nt][j] = 0.0f;

    #pragma unroll 1
    for (int c = 0; c < NCH_PER; c++) {
        if (c + 2 < NCH_PER) issueB((c + 2) % 3, c + 2);
        else CP_COMMIT();

        const uint32_t stA = sb + SM_A + (uint32_t)(c & 1) * A_TILE_B;
        const uint32_t stB = sb + SM_B + (uint32_t)(c % 3) * B_TILE_B;

        #pragma unroll
        for (int ks = 0; ks < 4; ks++) {
            uint32_t af[2][4], bf[4][2];
            #pragma unroll
            for (int mt = 0; mt < 2; mt++)
                LDSM4(af[mt][0], af[mt][1], af[mt][2], af[mt][3],
                      stA + a_loff + (uint32_t)(mt * 16 * ROWB + ks * 32));
            #pragma unroll
            for (int p = 0; p < 2; p++)
                LDSM4(bf[2*p][0], bf[2*p][1], bf[2*p+1][0], bf[2*p+1][1],
                      stB + b_loff + (uint32_t)(p * 16 * ROWB + ks * 32));
            #pragma unroll
            for (int mt = 0; mt < 2; mt++)
                #pragma unroll
                for (int nt = 0; nt < 4; nt++)
                    mma_f16_16n8k16(acc[mt][nt], af[mt], bf[nt]);
        }

        if (c + 1 < NCH_PER) {
            genA(c + 1, (c + 1) & 1, hn);
            if (c + 2 < NCH_PER) loadH(c + 2, hn);
            CP_WAIT1();           // B(c+1) arrived
            __syncthreads();      // A(c+1) + B(c+1) visible
        }
    }

    // -------- epilogue: Cpart = (acc [+ bias if kz==0]) / DIM ---------------
    const float inv = 1.0f / (float)DIM;
    const int re = bm + warp_m * 32 + qr;
    const int ce = bn + warp_n * 32 + qc * 2;
    #pragma unroll
    for (int mt = 0; mt < 2; mt++) {
        #pragma unroll
        for (int nt = 0; nt < 4; nt++) {
            int col = ce + nt * 8;
            float2 bv = make_float2(0.0f, 0.0f);
            if (kz == 0) bv = *(const float2*)(biasP0 + col);
            int row = re + mt * 16;
            float2 o0, o1;
            o0.x = (acc[mt][nt][0] + bv.x) * inv;
            o0.y = (acc[mt][nt][1] + bv.y) * inv;
            o1.x = (acc[mt][nt][2] + bv.x) * inv;
            o1.y = (acc[mt][nt][3] + bv.y) * inv;
            *(float2*)(C + (size_t)row * DIM + col)       = o0;
            *(float2*)(C + (size_t)(row + 8) * DIM + col) = o1;
        }
    }
}

// ---------------------------------------------------------------------------
// Launch
// ---------------------------------------------------------------------------
extern "C" void kernel_launch(void* const* d_in, const int* in_sizes, int n_in,
                              void* d_out, int out_size) {
    const float* x        = (const float*)d_in[0];
    const float* coefs    = (const float*)d_in[1];
    const float* alphas   = (const float*)d_in[2];
    const float* ln_scale = (const float*)d_in[3];
    const float* ln_bias  = (const float*)d_in[4];
    float* out = (float*)d_out;

    float* p0;   cudaGetSymbolAddress((void**)&p0,   g_p0);
    float* p1;   cudaGetSymbolAddress((void**)&p1,   g_p1);
    __half* Bn;  cudaGetSymbolAddress((void**)&Bn,   g_Bn);
    float* bias; cudaGetSymbolAddress((void**)&bias, g_bias);
    float* jc;   cudaGetSymbolAddress((void**)&jc,   g_jc);

    cudaFuncSetAttribute(fused_layer,
                         cudaFuncAttributeMaxDynamicSharedMemorySize,
                         SMEM_FUSED_BYTES);

    {
        int total = NLAYERS * DIM * KRED;
        build_Bn<<<(total + 255) / 256, 256>>>(coefs, Bn);
        build_bias<<<NLAYERS * DIM, 128>>>(coefs, alphas, bias, jc);
    }

    dim3 ggrid(BATCH / 64, DIM / 128, 2);   // (128, 2, 2) = 512 CTAs

    // Layer 0: x -> p0 (two K-split partials)
    fused_layer<<<ggrid, 256, SMEM_FUSED_BYTES>>>(
        x, nullptr, Bn, bias, ln_scale, ln_bias, jc, p0);

    // Layer 1: h = p0_half0 + p0_half1 (fused) -> p1 partials
    fused_layer<<<ggrid, 256, SMEM_FUSED_BYTES>>>(
        p0, p0 + (size_t)BATCH * DIM, Bn + (size_t)DIM * KRED, bias + DIM,
        ln_scale + DIM, ln_bias + DIM, jc + 8, p1);

    // Final combine: out = p1_half0 + p1_half1
    combine<<<(BATCH * DIM / 4) / 256, 256>>>(p1, out);
}

// round 15
// speedup vs baseline: 1.3640x; 1.3640x over previous
#include <cuda_runtime.h>
#include <cuda_fp16.h>
#include <math.h>
#include <stdint.h>

#define BATCH   8192
#define DIM     256
#define KRED    1024
#define NCOEF   5
#define NLAYERS 2
#define LN_EPS  1e-6f

// ---------------------------------------------------------------------------
// Scratch
// ---------------------------------------------------------------------------
__device__ float  g_h [BATCH * DIM];
__device__ __half g_Bn[NLAYERS * DIM * KRED];
__device__ float  g_bias[NLAYERS * DIM];
__device__ float  g_jc[NLAYERS * 8];

// ---------------------------------------------------------------------------
// Helpers
// ---------------------------------------------------------------------------
__device__ __forceinline__ uint32_t smem_u32(const void* p) {
    uint32_t a;
    asm("{ .reg .u64 t; cvta.to.shared.u64 t, %1; cvt.u32.u64 %0, t; }"
        : "=r"(a) : "l"(p));
    return a;
}
__device__ __forceinline__ float tanh_fast(float v) {
    float r;
    asm("tanh.approx.f32 %0, %1;" : "=f"(r) : "f"(v));
    return r;
}
__device__ __forceinline__ void mma_f16_16n8k16(float* d, const uint32_t* a,
                                                const uint32_t* b) {
    asm volatile(
        "mma.sync.aligned.m16n8k16.row.col.f32.f16.f16.f32 "
        "{%0,%1,%2,%3}, {%4,%5,%6,%7}, {%8,%9}, {%0,%1,%2,%3};"
        : "+f"(d[0]), "+f"(d[1]), "+f"(d[2]), "+f"(d[3])
        : "r"(a[0]), "r"(a[1]), "r"(a[2]), "r"(a[3]),
          "r"(b[0]), "r"(b[1]));
}
#define LDSM4(r0, r1, r2, r3, addr) \
    asm volatile("ldmatrix.sync.aligned.m8n8.x4.shared.b16 {%0,%1,%2,%3}, [%4];" \
        : "=r"(r0), "=r"(r1), "=r"(r2), "=r"(r3) : "r"(addr))
#define CP_ASYNC16(dst, src) \
    asm volatile("cp.async.cg.shared.global [%0], [%1], 16;" \
        :: "r"(dst), "l"(src))
#define CP_COMMIT()  asm volatile("cp.async.commit_group;" ::: "memory")
#define CP_WAIT2()   asm volatile("cp.async.wait_group 2;"  ::: "memory")

// ---------------------------------------------------------------------------
// build Bn[l][o][k], k = i*4 + (c-1), fp16
// ---------------------------------------------------------------------------
__global__ void build_Bn(const float* __restrict__ coefs,
                         __half* __restrict__ Bn) {
    int idx = blockIdx.x * blockDim.x + threadIdx.x;
    const int total = NLAYERS * DIM * KRED;
    if (idx >= total) return;
    int k = idx & (KRED - 1);
    int o = (idx >> 10) & (DIM - 1);
    int l = idx >> 18;
    int i = k >> 2;
    int c = (k & 3) + 1;
    Bn[idx] = __float2half_rn(
        coefs[(((size_t)(l * DIM + i)) * DIM + o) * NCOEF + c]);
}

// ---------------------------------------------------------------------------
// bias[l][o] = sum_i coefs[l][i][o][0]; Jacobi coefficient table
// ---------------------------------------------------------------------------
__global__ void __launch_bounds__(128)
build_bias(const float* __restrict__ coefs, const float* __restrict__ alphas,
           float* __restrict__ bias, float* __restrict__ jc) {
    int lo = blockIdx.x;
    int l = lo >> 8, o = lo & 255;
    float s = 0.0f;
    for (int i = threadIdx.x; i < DIM; i += 128)
        s += coefs[(((size_t)(l * DIM + i)) * DIM + o) * NCOEF];
    #pragma unroll
    for (int off = 16; off; off >>= 1) s += __shfl_xor_sync(0xFFFFFFFFu, s, off);
    __shared__ float red[4];
    if ((threadIdx.x & 31) == 0) red[threadIdx.x >> 5] = s;
    __syncthreads();
    if (threadIdx.x == 0)
        bias[lo] = red[0] + red[1] + red[2] + red[3];

    if (o == 0 && threadIdx.x == 0) {
        float a = tanhf(alphas[l]);
        jc[l * 8 + 0] = a + 1.0f;
        #pragma unroll
        for (int k = 2; k <= 4; k++) {
            float kf = (float)k;
            float t  = 2.0f * kf + 2.0f * a;
            float A  = 2.0f * kf * (kf + 2.0f * a) * (t - 2.0f);
            float B  = (t - 1.0f) * t * (t - 2.0f);
            float Cc = 2.0f * (kf + a - 1.0f) * (kf + a - 1.0f) * t;
            jc[l * 8 + (k - 1)]     = B / A;
            jc[l * 8 + 3 + (k - 1)] = Cc / A;
        }
        jc[l * 8 + 7] = 0.0f;
    }
}

// ---------------------------------------------------------------------------
// Fused layer: LN + tanh + Jacobi A-gen + fp16 HMMA GEMM.
// CTA tile 64(M) x 128(N), BK=64, 256 threads, 8 warps (2m x 4n, 32x32).
// 4-stage B ring (wait_group 2), 2 A buffers, register-double-buffered
// fragments, genA/issueB hoisted ahead of the MMA block.
// ---------------------------------------------------------------------------
#define BK        64
#define NCHUNK    (KRED / BK)         // 16
#define ROWB      144
#define A_TILE_B  (64 * ROWB)         // 9216
#define B_TILE_B  (128 * ROWB)        // 18432
#define SM_A      1024
#define SM_B      (1024 + 2 * A_TILE_B)   // 19456
#define SMEM_FUSED_BYTES (1024 + 2 * A_TILE_B + 4 * B_TILE_B)  // 93184

__global__ void __launch_bounds__(256, 2)
fused_layer(const float* __restrict__ h,
            const __half* __restrict__ Bn,
            const float* __restrict__ biasP0,
            const float* __restrict__ lnscale,
            const float* __restrict__ lnbias,
            const float* __restrict__ jc,
            float* __restrict__ C) {
    extern __shared__ char sm[];
    const uint32_t sb = smem_u32(sm);
    float2* stats = (float2*)sm;      // 64 rows

    const int tid = threadIdx.x;
    const int lid = tid & 31;
    const int wid = tid >> 5;
    const int warp_m = wid & 1;
    const int warp_n = wid >> 1;
    const int qr = lid >> 2;
    const int qc = lid & 3;

    const int bm = blockIdx.x * 64;
    const int bn = blockIdx.y * 128;

    // Jacobi coefficients hoisted to registers (uniform)
    const float4 j0 = __ldg((const float4*)jc);       // p1c, bb0, bb1, bb2
    const float4 j1 = __ldg((const float4*)jc + 1);   // cc0, cc1, cc2, -

    // B stage loader
    auto issueB = [&](int ch) {
        const uint32_t st = sb + SM_B + (uint32_t)(ch & 3) * B_TILE_B;
        #pragma unroll
        for (int it = 0; it < 4; it++) {
            int idx = tid + it * 256;
            int row = idx >> 3, q8 = idx & 7;
            const __half* gb = Bn + (size_t)(bn + row) * KRED + ch * BK + q8 * 8;
            CP_ASYNC16(st + row * ROWB + q8 * 16, gb);
        }
        CP_COMMIT();
    };

    // h prefetch: row r0 = tid>>2, float4 col (tid&3)*4
    const int i4 = tid & 3;
    const int r0 = tid >> 2;
    auto loadH = [&](int ch, float4& v) {
        v = *(const float4*)(h + (size_t)(bm + r0) * DIM + ch * 16 + i4 * 4);
    };

    // A generation: row r0, 4 input dims -> 16 halves (32 B)
    auto genA = [&](int ch, float4 v) {
        float4 sc = *(const float4*)(lnscale + ch * 16 + i4 * 4);
        float4 bi = *(const float4*)(lnbias  + ch * 16 + i4 * 4);
        float2 st = stats[r0];
        float xv[4]  = {v.x, v.y, v.z, v.w};
        float scv[4] = {sc.x, sc.y, sc.z, sc.w};
        float biv[4] = {bi.x, bi.y, bi.z, bi.w};
        uint32_t oh[8];
        #pragma unroll
        for (int e = 0; e < 4; e++) {
            float x  = tanh_fast((xv[e] - st.x) * st.y * scv[e] + biv[e]);
            float P1 = j0.x * x;
            float P2 = j0.y * x * P1 - j1.x;
            float P3 = j0.z * x * P2 - j1.y * P1;
            float P4 = j0.w * x * P3 - j1.z * P2;
            __half2 h0 = __floats2half2_rn(P1, P2);
            __half2 h1 = __floats2half2_rn(P3, P4);
            oh[2 * e]     = *(uint32_t*)&h0;
            oh[2 * e + 1] = *(uint32_t*)&h1;
        }
        uint4* dst = (uint4*)(sm + SM_A + (ch & 1) * A_TILE_B + r0 * ROWB + i4 * 32);
        dst[0] = make_uint4(oh[0], oh[1], oh[2], oh[3]);
        dst[1] = make_uint4(oh[4], oh[5], oh[6], oh[7]);
    };

    // -------- prologue ------------------------------------------------------
    issueB(0);
    issueB(1);
    issueB(2);

    {   // LN stats: warp w -> rows w*8 .. w*8+7
        #pragma unroll 1
        for (int j = 0; j < 8; j++) {
            int row = wid * 8 + j;
            const float4* p = (const float4*)(h + (size_t)(bm + row) * DIM) + lid * 2;
            float4 u = p[0], v = p[1];
            float s  = u.x + u.y + u.z + u.w + v.x + v.y + v.z + v.w;
            float s2 = u.x*u.x + u.y*u.y + u.z*u.z + u.w*u.w
                     + v.x*v.x + v.y*v.y + v.z*v.z + v.w*v.w;
            #pragma unroll
            for (int off = 16; off; off >>= 1) {
                s  += __shfl_xor_sync(0xFFFFFFFFu, s,  off);
                s2 += __shfl_xor_sync(0xFFFFFFFFu, s2, off);
            }
            if (lid == 0) {
                float mu  = s * (1.0f / DIM);
                float var = s2 * (1.0f / DIM) - mu * mu;
                stats[row] = make_float2(mu, rsqrtf(var + LN_EPS));
            }
        }
    }
    __syncthreads();              // stats visible

    float4 hn;
    loadH(0, hn);
    genA(0, hn);
    loadH(1, hn);

    CP_WAIT2();                   // B(0) arrived
    __syncthreads();              // A(0) + B(0) visible

    // ldmatrix lane offsets
    const uint32_t a_loff =
        (uint32_t)((warp_m * 32 + (lid & 15)) * ROWB + ((lid >> 4) << 4));
    const uint32_t b_loff =
        (uint32_t)((warp_n * 32 + ((lid & 7) | ((lid >> 4) << 3))) * ROWB +
                   (((lid >> 3) & 1) << 4));

    float acc[2][4][4];
    #pragma unroll
    for (int mt = 0; mt < 2; mt++)
        #pragma unroll
        for (int nt = 0; nt < 4; nt++)
            #pragma unroll
            for (int j = 0; j < 4; j++) acc[mt][nt][j] = 0.0f;

    uint32_t af[2][2][4], bf[2][4][2];

    #pragma unroll 1
    for (int c = 0; c < NCHUNK; c++) {
        const uint32_t stA = sb + SM_A + (uint32_t)(c & 1) * A_TILE_B;
        const uint32_t stB = sb + SM_B + (uint32_t)(c & 3) * B_TILE_B;

        // preload ks=0 fragments (latency overlapped by genA below)
        #pragma unroll
        for (int mt = 0; mt < 2; mt++)
            LDSM4(af[0][mt][0], af[0][mt][1], af[0][mt][2], af[0][mt][3],
                  stA + a_loff + (uint32_t)(mt * 16 * ROWB));
        #pragma unroll
        for (int p = 0; p < 2; p++)
            LDSM4(bf[0][2*p][0], bf[0][2*p][1], bf[0][2*p+1][0], bf[0][2*p+1][1],
                  stB + b_loff + (uint32_t)(p * 16 * ROWB));

        // hoisted producer work: B(c+3) issue + A(c+1) generation
        if (c + 3 < NCHUNK) issueB(c + 3);
        else CP_COMMIT();
        if (c + 1 < NCHUNK) {
            genA(c + 1, hn);
            if (c + 2 < NCHUNK) loadH(c + 2, hn);
        }

        #pragma unroll
        for (int ks = 0; ks < 4; ks++) {
            const int cur = ks & 1;
            if (ks < 3) {
                const int nxt = cur ^ 1;
                #pragma unroll
                for (int mt = 0; mt < 2; mt++)
                    LDSM4(af[nxt][mt][0], af[nxt][mt][1],
                          af[nxt][mt][2], af[nxt][mt][3],
                          stA + a_loff + (uint32_t)(mt * 16 * ROWB + (ks + 1) * 32));
                #pragma unroll
                for (int p = 0; p < 2; p++)
                    LDSM4(bf[nxt][2*p][0], bf[nxt][2*p][1],
                          bf[nxt][2*p+1][0], bf[nxt][2*p+1][1],
                          stB + b_loff + (uint32_t)(p * 16 * ROWB + (ks + 1) * 32));
            }
            #pragma unroll
            for (int mt = 0; mt < 2; mt++)
                #pragma unroll
                for (int nt = 0; nt < 4; nt++)
                    mma_f16_16n8k16(acc[mt][nt], af[cur][mt], bf[cur][nt]);
        }

        if (c + 1 < NCHUNK) {
            CP_WAIT2();           // B(c+1) arrived
            __syncthreads();      // A(c+1) + B(c+1) visible
        }
    }

    // -------- epilogue: C = (acc + bias) / DIM ------------------------------
    const float inv = 1.0f / (float)DIM;
    const int re = bm + warp_m * 32 + qr;
    const int ce = bn + warp_n * 32 + qc * 2;
    #pragma unroll
    for (int mt = 0; mt < 2; mt++) {
        #pragma unroll
        for (int nt = 0; nt < 4; nt++) {
            int col = ce + nt * 8;
            float2 bv = *(const float2*)(biasP0 + col);
            int row = re + mt * 16;
            float2 o0, o1;
            o0.x = (acc[mt][nt][0] + bv.x) * inv;
            o0.y = (acc[mt][nt][1] + bv.y) * inv;
            o1.x = (acc[mt][nt][2] + bv.x) * inv;
            o1.y = (acc[mt][nt][3] + bv.y) * inv;
            *(float2*)(C + (size_t)row * DIM + col)       = o0;
            *(float2*)(C + (size_t)(row + 8) * DIM + col) = o1;
        }
    }
}

// ---------------------------------------------------------------------------
// Launch
// ---------------------------------------------------------------------------
extern "C" void kernel_launch(void* const* d_in, const int* in_sizes, int n_in,
                              void* d_out, int out_size) {
    const float* x        = (const float*)d_in[0];
    const float* coefs    = (const float*)d_in[1];
    const float* alphas   = (const float*)d_in[2];
    const float* ln_scale = (const float*)d_in[3];
    const float* ln_bias  = (const float*)d_in[4];
    float* out = (float*)d_out;

    float* hbuf; cudaGetSymbolAddress((void**)&hbuf, g_h);
    __half* Bn;  cudaGetSymbolAddress((void**)&Bn,   g_Bn);
    float* bias; cudaGetSymbolAddress((void**)&bias, g_bias);
    float* jc;   cudaGetSymbolAddress((void**)&jc,   g_jc);

    cudaFuncSetAttribute(fused_layer,
                         cudaFuncAttributeMaxDynamicSharedMemorySize,
                         SMEM_FUSED_BYTES);

    {
        int total = NLAYERS * DIM * KRED;
        build_Bn<<<(total + 255) / 256, 256>>>(coefs, Bn);
        build_bias<<<NLAYERS * DIM, 128>>>(coefs, alphas, bias, jc);
    }

    dim3 ggrid(BATCH / 64, DIM / 128);   // (128, 2) = 256 CTAs

    fused_layer<<<ggrid, 256, SMEM_FUSED_BYTES>>>(
        x, Bn, bias, ln_scale, ln_bias, jc, hbuf);

    fused_layer<<<ggrid, 256, SMEM_FUSED_BYTES>>>(
        hbuf, Bn + (size_t)DIM * KRED, bias + DIM,
        ln_scale + DIM, ln_bias + DIM, jc + 8, out);
}